// round 3
// baseline (speedup 1.0000x reference)
#include <cuda_runtime.h>
#include <cstdint>

#define NB 64
#define NT 1024
#define NI 256
#define NH 512
#define NO 256

// ---------------- scratch (device globals: the sanctioned no-alloc path) ----------------
__device__ float g_xh[(size_t)NB * NT * NH];   // 128 MB: [t][b][h]
__device__ float g_hs[(size_t)NB * NT * NH];   // 128 MB: [b][t][h]
__device__ float g_hbuf[2][NB * NH];           // double-buffered h state
__device__ unsigned g_flags[128];              // per-CTA step counters
__device__ unsigned g_bar_cnt = 0;
__device__ volatile unsigned g_bar_sense = 0;

// ---------------- helpers ----------------
__device__ __forceinline__ void fma2(unsigned long long& d, unsigned long long a,
                                     unsigned long long b) {
    asm("fma.rn.f32x2 %0, %1, %2, %0;" : "+l"(d) : "l"(a), "l"(b));
}
__device__ __forceinline__ float f2sum(unsigned long long v) {
    float lo, hi;
    asm("mov.b64 {%0, %1}, %2;" : "=f"(lo), "=f"(hi) : "l"(v));
    return lo + hi;
}

// =====================================================================================
// GEMM: C[M,N] = A[M,K] @ B[K,N] + bias.  BM=BN=64, BK=32, 256 threads, thread tile 4x4.
// f32x2 accumulators over k-parity pairs (no packing MOVs needed).
// MODE 0: A = x, writes g_xh in [t][b][h] layout (bias = b_h).
// MODE 1: A = g_hs, writes C = out in [b][t][o] layout (bias = b_y).
// =====================================================================================
template <int MODE>
__global__ __launch_bounds__(256) void gemm_kernel(const float* __restrict__ A,
                                                   const float* __restrict__ Bm,
                                                   const float* __restrict__ bias,
                                                   float* __restrict__ C, int K) {
    __shared__ __align__(16) float As[64 * 36];  // [m][k], pitch 36
    __shared__ __align__(16) float Bs[64 * 36];  // [n][k] (transposed), pitch 36

    const int tid = threadIdx.x;
    const int tn = tid & 15, tm = tid >> 4;
    const int n0 = blockIdx.x * 64;
    const int m0 = blockIdx.y * 64;
    const int N = gridDim.x * 64;  // 512 (mode 0) or 256 (mode 1) == ldb

    const float* Ap = (MODE == 0) ? A : (const float*)g_hs;

    unsigned long long acc[4][4];
#pragma unroll
    for (int i = 0; i < 4; i++)
#pragma unroll
        for (int j = 0; j < 4; j++) acc[i][j] = 0ULL;

    const int a_m = tid >> 2, a_s = (tid & 3) * 8;  // A staging: 64 rows x 32 cols
    const int b_k = tid >> 3, b_s = (tid & 7) * 8;  // B staging: 32 rows x 64 cols

    for (int k0 = 0; k0 < K; k0 += 32) {
        const float* ap = &Ap[(size_t)(m0 + a_m) * K + k0 + a_s];
        float4 av0 = *(const float4*)(ap);
        float4 av1 = *(const float4*)(ap + 4);
        const float* bp = &Bm[(size_t)(k0 + b_k) * N + n0 + b_s];
        float4 bv0 = *(const float4*)(bp);
        float4 bv1 = *(const float4*)(bp + 4);

        __syncthreads();  // previous tile fully consumed
        *(float4*)&As[a_m * 36 + a_s] = av0;
        *(float4*)&As[a_m * 36 + a_s + 4] = av1;
        Bs[(b_s + 0) * 36 + b_k] = bv0.x;
        Bs[(b_s + 1) * 36 + b_k] = bv0.y;
        Bs[(b_s + 2) * 36 + b_k] = bv0.z;
        Bs[(b_s + 3) * 36 + b_k] = bv0.w;
        Bs[(b_s + 4) * 36 + b_k] = bv1.x;
        Bs[(b_s + 5) * 36 + b_k] = bv1.y;
        Bs[(b_s + 6) * 36 + b_k] = bv1.z;
        Bs[(b_s + 7) * 36 + b_k] = bv1.w;
        __syncthreads();

#pragma unroll
        for (int kk = 0; kk < 32; kk += 4) {
            unsigned long long av[4][2], bv[4][2];
#pragma unroll
            for (int i = 0; i < 4; i++) {
                ulonglong2 t = *(const ulonglong2*)&As[(tm * 4 + i) * 36 + kk];
                av[i][0] = t.x;
                av[i][1] = t.y;
            }
#pragma unroll
            for (int j = 0; j < 4; j++) {
                ulonglong2 t = *(const ulonglong2*)&Bs[(tn + 16 * j) * 36 + kk];
                bv[j][0] = t.x;
                bv[j][1] = t.y;
            }
#pragma unroll
            for (int i = 0; i < 4; i++)
#pragma unroll
                for (int j = 0; j < 4; j++) {
                    fma2(acc[i][j], av[i][0], bv[j][0]);
                    fma2(acc[i][j], av[i][1], bv[j][1]);
                }
        }
    }

#pragma unroll
    for (int j = 0; j < 4; j++) {
        int n = n0 + tn + 16 * j;
        float bz = bias[n];
#pragma unroll
        for (int i = 0; i < 4; i++) {
            int m = m0 + tm * 4 + i;
            float v = f2sum(acc[i][j]) + bz;
            if (MODE == 0) {
                int b = m >> 10, t = m & 1023;  // m = b*1024 + t
                g_xh[((size_t)t * NB + b) * NH + n] = v;
            } else {
                C[(size_t)m * NO + n] = v;
            }
        }
    }
}

// =====================================================================================
// Scan: 128 persistent CTAs = 16 batch-groups(4 rows) x 8 col-slices(64 cols).
// W_hh slice resident in SMEM; h exchanged via L2 with per-group flags.
// =====================================================================================
__global__ __launch_bounds__(256) void scan_kernel(const float* __restrict__ W_hh) {
    extern __shared__ __align__(16) float smem[];
    float* Ws = smem;                        // [64][516]  c-major, k contiguous
    float* hsm = smem + 64 * 516;            // [4][516]
    float* red = smem + 64 * 516 + 4 * 516;  // [16][4][64]

    const int tid = threadIdx.x;
    const int g = blockIdx.x >> 3;  // batch group (4 rows)
    const int s = blockIdx.x & 7;   // column slice (64 cols)
    const int cc = tid & 15, ks = tid >> 4;  // compute mapping
    const int rr = tid >> 6, c = tid & 63;   // reduce/io mapping

    // stage W slice transposed: Ws[c][k] = W_hh[k][s*64+c]
    for (int idx = tid; idx < NH * 64; idx += 256) {
        int k = idx >> 6, cl = idx & 63;
        Ws[cl * 516 + k] = W_hh[(size_t)k * NH + s * 64 + cl];
    }
    // h0 = 0
    for (int idx = tid; idx < 4 * 516; idx += 256) hsm[idx] = 0.f;
    if (tid == 0) ((volatile unsigned*)g_flags)[blockIdx.x] = 0u;
    __threadfence();
    __syncthreads();

    // one grid barrier per launch (all 128 CTAs co-resident at 1 CTA/SM)
    if (tid == 0) {
        unsigned sense = g_bar_sense;
        __threadfence();
        if (atomicAdd(&g_bar_cnt, 1u) == 127u) {
            g_bar_cnt = 0u;
            __threadfence();
            g_bar_sense = sense ^ 1u;
        } else {
            while (g_bar_sense == sense) {
            }
        }
        __threadfence();
    }
    __syncthreads();

    const int k0 = ks * 32;
    const float* Wp = Ws + cc * 516;

    for (int t = 0; t < NT; t++) {
        // xh prefetch: independent of the flag wait, issued early
        float xval = g_xh[((size_t)t * NB + g * 4 + rr) * NH + s * 64 + c];

        // partials: thread covers 4 rows x 4 cols (c strided 16) x 32 k
        unsigned long long acc[4][4];
#pragma unroll
        for (int r = 0; r < 4; r++)
#pragma unroll
            for (int cp = 0; cp < 4; cp++) acc[r][cp] = 0ULL;

#pragma unroll
        for (int kk = 0; kk < 32; kk += 4) {
            ulonglong2 hv[4];
#pragma unroll
            for (int r = 0; r < 4; r++)
                hv[r] = *(const ulonglong2*)&hsm[r * 516 + k0 + kk];
#pragma unroll
            for (int cp = 0; cp < 4; cp++) {
                ulonglong2 wv = *(const ulonglong2*)&Wp[cp * (16 * 516) + k0 + kk];
#pragma unroll
                for (int r = 0; r < 4; r++) {
                    fma2(acc[r][cp], wv.x, hv[r].x);
                    fma2(acc[r][cp], wv.y, hv[r].y);
                }
            }
        }
#pragma unroll
        for (int r = 0; r < 4; r++)
#pragma unroll
            for (int cp = 0; cp < 4; cp++)
                red[(ks * 4 + r) * 64 + cc + 16 * cp] = f2sum(acc[r][cp]);
        __syncthreads();

        // k-split reduction + tanh
        float v = xval;
#pragma unroll
        for (int q = 0; q < 16; q++) v += red[(q * 4 + rr) * 64 + c];
        float h = tanhf(v);

        const int row = g * 4 + rr, gc = s * 64 + c;
        g_hbuf[(t + 1) & 1][row * NH + gc] = h;
        g_hs[((size_t)row * NT + t) * NH + gc] = h;
        __threadfence();
        __syncthreads();
        if (tid == 0) ((volatile unsigned*)g_flags)[blockIdx.x] = (unsigned)(t + 1);

        if (t + 1 < NT) {
            if (tid < 8) {
                volatile unsigned* fl = &((volatile unsigned*)g_flags)[g * 8 + tid];
                while (*fl < (unsigned)(t + 1)) {
                }
            }
            __threadfence();
            __syncthreads();
            // reload full h rows for this group from the just-filled buffer
            const float* src = &g_hbuf[(t + 1) & 1][(g * 4) * NH];
            for (int idx = tid; idx < (4 * NH) / 4; idx += 256) {
                int r = idx >> 7, kv = (idx & 127) * 4;
                *(float4*)&hsm[r * 516 + kv] = *(const float4*)&src[r * NH + kv];
            }
            __syncthreads();
        }
    }
}

// =====================================================================================
extern "C" void kernel_launch(void* const* d_in, const int* in_sizes, int n_in,
                              void* d_out, int out_size) {
    const float* x = (const float*)d_in[0];
    const float* W_xh = (const float*)d_in[1];
    const float* W_hh = (const float*)d_in[2];
    const float* b_h = (const float*)d_in[3];
    const float* W_hy = (const float*)d_in[4];
    const float* b_y = (const float*)d_in[5];
    float* out = (float*)d_out;

    const int scan_smem = (64 * 516 + 4 * 516 + 16 * 4 * 64) * (int)sizeof(float);
    cudaFuncSetAttribute(scan_kernel, cudaFuncAttributeMaxDynamicSharedMemorySize,
                         scan_smem);

    // xh = x @ W_xh + b_h   (M=65536, N=512, K=256) -> g_xh [t][b][h]
    gemm_kernel<0><<<dim3(8, 1024), 256>>>(x, W_xh, b_h, nullptr, NI);
    // recurrence
    scan_kernel<<<128, 256, scan_smem>>>(W_hh);
    // out = hs @ W_hy + b_y (M=65536, N=256, K=512)
    gemm_kernel<1><<<dim3(4, 1024), 256>>>(nullptr, W_hy, b_y, out, NH);
}

// round 4
// speedup vs baseline: 1.8633x; 1.8633x over previous
#include <cuda_runtime.h>
#include <cstdint>

#define NB 64
#define NT 1024
#define NI 256
#define NH 512
#define NO 256

// ---------------- scratch (device globals: the sanctioned no-alloc path) ----------------
__device__ float g_xh[(size_t)NB * NT * NH];   // 128 MB: [t][b][h]
__device__ float g_hs[(size_t)NB * NT * NH];   // 128 MB: [b][t][h]

// ---------------- helpers ----------------
__device__ __forceinline__ void fma2(unsigned long long& d, unsigned long long a,
                                     unsigned long long b) {
    asm("fma.rn.f32x2 %0, %1, %2, %0;" : "+l"(d) : "l"(a), "l"(b));
}
__device__ __forceinline__ float f2sum(unsigned long long v) {
    float lo, hi;
    asm("mov.b64 {%0, %1}, %2;" : "=f"(lo), "=f"(hi) : "l"(v));
    return lo + hi;
}
__device__ __forceinline__ unsigned smem_u32(const void* p) {
    unsigned a;
    asm("{ .reg .u64 t; cvta.to.shared.u64 t, %1; cvt.u32.u64 %0, t; }"
        : "=r"(a) : "l"(p));
    return a;
}

// =====================================================================================
// GEMM: C[M,N] = A[M,K] @ B[K,N] + bias.  BM=BN=64, BK=32, 256 threads, thread tile 4x4.
// MODE 0: A = x, writes g_xh in [t][b][h] layout (bias = b_h).
// MODE 1: A = g_hs, writes C = out in [b][t][o] layout (bias = b_y).
// =====================================================================================
template <int MODE>
__global__ __launch_bounds__(256) void gemm_kernel(const float* __restrict__ A,
                                                   const float* __restrict__ Bm,
                                                   const float* __restrict__ bias,
                                                   float* __restrict__ C, int K) {
    __shared__ __align__(16) float As[64 * 36];  // [m][k], pitch 36
    __shared__ __align__(16) float Bs[64 * 36];  // [n][k] (transposed), pitch 36

    const int tid = threadIdx.x;
    const int tn = tid & 15, tm = tid >> 4;
    const int n0 = blockIdx.x * 64;
    const int m0 = blockIdx.y * 64;
    const int N = gridDim.x * 64;  // 512 (mode 0) or 256 (mode 1) == ldb

    const float* Ap = (MODE == 0) ? A : (const float*)g_hs;

    unsigned long long acc[4][4];
#pragma unroll
    for (int i = 0; i < 4; i++)
#pragma unroll
        for (int j = 0; j < 4; j++) acc[i][j] = 0ULL;

    const int a_m = tid >> 2, a_s = (tid & 3) * 8;  // A staging: 64 rows x 32 cols
    const int b_k = tid >> 3, b_s = (tid & 7) * 8;  // B staging: 32 rows x 64 cols

    for (int k0 = 0; k0 < K; k0 += 32) {
        const float* ap = &Ap[(size_t)(m0 + a_m) * K + k0 + a_s];
        float4 av0 = *(const float4*)(ap);
        float4 av1 = *(const float4*)(ap + 4);
        const float* bp = &Bm[(size_t)(k0 + b_k) * N + n0 + b_s];
        float4 bv0 = *(const float4*)(bp);
        float4 bv1 = *(const float4*)(bp + 4);

        __syncthreads();  // previous tile fully consumed
        *(float4*)&As[a_m * 36 + a_s] = av0;
        *(float4*)&As[a_m * 36 + a_s + 4] = av1;
        Bs[(b_s + 0) * 36 + b_k] = bv0.x;
        Bs[(b_s + 1) * 36 + b_k] = bv0.y;
        Bs[(b_s + 2) * 36 + b_k] = bv0.z;
        Bs[(b_s + 3) * 36 + b_k] = bv0.w;
        Bs[(b_s + 4) * 36 + b_k] = bv1.x;
        Bs[(b_s + 5) * 36 + b_k] = bv1.y;
        Bs[(b_s + 6) * 36 + b_k] = bv1.z;
        Bs[(b_s + 7) * 36 + b_k] = bv1.w;
        __syncthreads();

#pragma unroll
        for (int kk = 0; kk < 32; kk += 4) {
            unsigned long long av[4][2], bv[4][2];
#pragma unroll
            for (int i = 0; i < 4; i++) {
                ulonglong2 t = *(const ulonglong2*)&As[(tm * 4 + i) * 36 + kk];
                av[i][0] = t.x;
                av[i][1] = t.y;
            }
#pragma unroll
            for (int j = 0; j < 4; j++) {
                ulonglong2 t = *(const ulonglong2*)&Bs[(tn + 16 * j) * 36 + kk];
                bv[j][0] = t.x;
                bv[j][1] = t.y;
            }
#pragma unroll
            for (int i = 0; i < 4; i++)
#pragma unroll
                for (int j = 0; j < 4; j++) {
                    fma2(acc[i][j], av[i][0], bv[j][0]);
                    fma2(acc[i][j], av[i][1], bv[j][1]);
                }
        }
    }

#pragma unroll
    for (int j = 0; j < 4; j++) {
        int n = n0 + tn + 16 * j;
        float bz = bias[n];
#pragma unroll
        for (int i = 0; i < 4; i++) {
            int m = m0 + tm * 4 + i;
            float v = f2sum(acc[i][j]) + bz;
            if (MODE == 0) {
                int b = m >> 10, t = m & 1023;  // m = b*1024 + t
                g_xh[((size_t)t * NB + b) * NH + n] = v;
            } else {
                C[(size_t)m * NO + n] = v;
            }
        }
    }
}

// =====================================================================================
// Scan: 16 independent clusters (one per 4-row batch group), 8 CTAs/cluster
// (one per 64-col slice). W_hh slice resident in SMEM for all 1024 steps.
// h state exchanged through DSMEM: each thread broadcasts its h value into all
// 8 CTAs' double-buffered h smem via st.shared::cluster; one cluster barrier
// per step. No L2 traffic, no fences, no flags on the step-critical path.
// =====================================================================================
__global__ __launch_bounds__(256) __cluster_dims__(8, 1, 1)
void scan_kernel(const float* __restrict__ W_hh) {
    extern __shared__ __align__(16) float smem[];
    float* Ws = smem;                          // [64][516]  c-major, k contiguous
    float* hsm = smem + 64 * 516;              // [2][4][516] double-buffered h
    float* red = smem + 64 * 516 + 2 * 4 * 516;  // [16][4][64]

    const int tid = threadIdx.x;
    unsigned s;  // column slice = rank within cluster
    asm("mov.u32 %0, %%cluster_ctarank;" : "=r"(s));
    const int g = blockIdx.x >> 3;            // batch group (4 rows)
    const int cc = tid & 15, ks = tid >> 4;   // compute mapping
    const int rr = tid >> 6, c = tid & 63;    // reduce/io mapping

    // stage W slice transposed: Ws[c][k] = W_hh[k][s*64+c]
    for (int idx = tid; idx < NH * 64; idx += 256) {
        int k = idx >> 6, cl = idx & 63;
        Ws[cl * 516 + k] = W_hh[(size_t)k * NH + s * 64 + cl];
    }
    // h0 = 0 in both buffers
    for (int idx = tid; idx < 2 * 4 * 516; idx += 256) hsm[idx] = 0.f;
    __syncthreads();

    // cluster sync: all CTAs' hsm zeroed before any remote store lands
    asm volatile("barrier.cluster.arrive.aligned;" ::: "memory");
    asm volatile("barrier.cluster.wait.aligned;" ::: "memory");

    // precompute peer hsm base addresses (mapa once, reuse every step)
    unsigned hsm_base = smem_u32(hsm);
    unsigned rem[8];
#pragma unroll
    for (int p = 0; p < 8; p++)
        asm("mapa.shared::cluster.u32 %0, %1, %2;"
            : "=r"(rem[p]) : "r"(hsm_base), "r"((unsigned)p));

    const int k0 = ks * 32;
    const float* Wp = Ws + cc * 516;
    const unsigned my_elem = (unsigned)(rr * 516 + s * 64 + c) * 4u;

    for (int t = 0; t < NT; t++) {
        // xh prefetch: global read, issued before the FMA block to hide DRAM
        float xval = g_xh[((size_t)t * NB + g * 4 + rr) * NH + s * 64 + c];

        const float* hcur = hsm + (t & 1) * (4 * 516);

        // partials: thread covers 4 rows x 4 cols (c strided 16) x 32 k
        unsigned long long acc[4][4];
#pragma unroll
        for (int r = 0; r < 4; r++)
#pragma unroll
            for (int cp = 0; cp < 4; cp++) acc[r][cp] = 0ULL;

#pragma unroll
        for (int kk = 0; kk < 32; kk += 4) {
            ulonglong2 hv[4];
#pragma unroll
            for (int r = 0; r < 4; r++)
                hv[r] = *(const ulonglong2*)&hcur[r * 516 + k0 + kk];
#pragma unroll
            for (int cp = 0; cp < 4; cp++) {
                ulonglong2 wv = *(const ulonglong2*)&Wp[cp * (16 * 516) + k0 + kk];
#pragma unroll
                for (int r = 0; r < 4; r++) {
                    fma2(acc[r][cp], wv.x, hv[r].x);
                    fma2(acc[r][cp], wv.y, hv[r].y);
                }
            }
        }
#pragma unroll
        for (int r = 0; r < 4; r++)
#pragma unroll
            for (int cp = 0; cp < 4; cp++)
                red[(ks * 4 + r) * 64 + cc + 16 * cp] = f2sum(acc[r][cp]);
        __syncthreads();

        // k-split reduction + tanh
        float v = xval;
#pragma unroll
        for (int q = 0; q < 16; q++) v += red[(q * 4 + rr) * 64 + c];
        float h = tanhf(v);

        // persist for the output GEMM (no intra-kernel ordering needed)
        g_hs[((size_t)(g * 4 + rr) * NT + t) * NH + s * 64 + c] = h;

        // broadcast h into every cluster CTA's NEXT h buffer via DSMEM
        unsigned off = (unsigned)(((t + 1) & 1) * (4 * 516) * 4) + my_elem;
#pragma unroll
        for (int p = 0; p < 8; p++)
            asm volatile("st.shared::cluster.f32 [%0], %1;"
                         :: "r"(rem[p] + off), "f"(h) : "memory");

        // one barrier per step: orders this step's remote stores before the
        // next step's reads, AND guarantees buffer (t+2)&1 is no longer read
        // before it gets overwritten two steps from now.
        asm volatile("barrier.cluster.arrive.aligned;" ::: "memory");
        asm volatile("barrier.cluster.wait.aligned;" ::: "memory");
    }
}

// =====================================================================================
extern "C" void kernel_launch(void* const* d_in, const int* in_sizes, int n_in,
                              void* d_out, int out_size) {
    const float* x = (const float*)d_in[0];
    const float* W_xh = (const float*)d_in[1];
    const float* W_hh = (const float*)d_in[2];
    const float* b_h = (const float*)d_in[3];
    const float* W_hy = (const float*)d_in[4];
    const float* b_y = (const float*)d_in[5];
    float* out = (float*)d_out;

    const int scan_smem =
        (64 * 516 + 2 * 4 * 516 + 16 * 4 * 64) * (int)sizeof(float);
    cudaFuncSetAttribute(scan_kernel, cudaFuncAttributeMaxDynamicSharedMemorySize,
                         scan_smem);

    // xh = x @ W_xh + b_h   (M=65536, N=512, K=256) -> g_xh [t][b][h]
    gemm_kernel<0><<<dim3(8, 1024), 256>>>(x, W_xh, b_h, nullptr, NI);
    // recurrence: 16 clusters x 8 CTAs
    scan_kernel<<<128, 256, scan_smem>>>(W_hh);
    // out = hs @ W_hy + b_y (M=65536, N=256, K=512)
    gemm_kernel<1><<<dim3(4, 1024), 256>>>(nullptr, W_hy, b_y, out, NH);
}

// round 5
// speedup vs baseline: 2.2614x; 1.2136x over previous
#include <cuda_runtime.h>
#include <cstdint>

#define NB 64
#define NT 1024
#define NI 256
#define NH 512
#define NO 256

// ---------------- scratch (device globals: the sanctioned no-alloc path) ----------------
__device__ float g_xh[(size_t)NB * NT * NH];   // 128 MB: [t][b][h]
__device__ float g_hs[(size_t)NB * NT * NH];   // 128 MB: [b][t][h]

// ---------------- helpers ----------------
__device__ __forceinline__ void fma2(unsigned long long& d, unsigned long long a,
                                     unsigned long long b) {
    asm("fma.rn.f32x2 %0, %1, %2, %0;" : "+l"(d) : "l"(a), "l"(b));
}
__device__ __forceinline__ float f2sum(unsigned long long v) {
    float lo, hi;
    asm("mov.b64 {%0, %1}, %2;" : "=f"(lo), "=f"(hi) : "l"(v));
    return lo + hi;
}
__device__ __forceinline__ unsigned smem_u32(const void* p) {
    unsigned a;
    asm("{ .reg .u64 t; cvta.to.shared.u64 t, %1; cvt.u32.u64 %0, t; }"
        : "=r"(a) : "l"(p));
    return a;
}
__device__ __forceinline__ void mbar_init(unsigned a, unsigned cnt) {
    asm volatile("mbarrier.init.shared.b64 [%0], %1;" ::"r"(a), "r"(cnt) : "memory");
}
__device__ __forceinline__ void mbar_arrive_expect_tx(unsigned a, unsigned bytes) {
    asm volatile("mbarrier.arrive.expect_tx.shared.b64 _, [%0], %1;"
                 ::"r"(a), "r"(bytes) : "memory");
}
__device__ __forceinline__ void mbar_wait_parity(unsigned a, unsigned parity) {
    unsigned done;
    asm volatile(
        "{\n\t.reg .pred p;\n\t"
        "mbarrier.try_wait.parity.acquire.cta.shared::cta.b64 p, [%1], %2;\n\t"
        "selp.b32 %0, 1, 0, p;\n\t}"
        : "=r"(done) : "r"(a), "r"(parity) : "memory");
    if (!done) {
        asm volatile(
            "{\n\t.reg .pred P1;\n\t"
            "WAIT_LOOP_%=:\n\t"
            "mbarrier.try_wait.parity.acquire.cta.shared::cta.b64 P1, [%0], %1, 0x989680;\n\t"
            "@P1 bra.uni WAIT_DONE_%=;\n\t"
            "bra.uni WAIT_LOOP_%=;\n\t"
            "WAIT_DONE_%=:\n\t}"
            ::"r"(a), "r"(parity) : "memory");
    }
}
__device__ __forceinline__ void st_async_f32(unsigned addr, float v, unsigned mbar) {
    asm volatile(
        "st.async.shared::cluster.mbarrier::complete_tx::bytes.f32 [%0], %1, [%2];"
        ::"r"(addr), "f"(v), "r"(mbar) : "memory");
}

// =====================================================================================
// GEMM: C[M,N] = A[M,K] @ B[K,N] + bias.  BM=BN=64, BK=32, 256 threads, thread tile 4x4.
// MODE 0: A = x, writes g_xh in [t][b][h] layout (bias = b_h).
// MODE 1: A = g_hs, writes C = out in [b][t][o] layout (bias = b_y).
// =====================================================================================
template <int MODE>
__global__ __launch_bounds__(256) void gemm_kernel(const float* __restrict__ A,
                                                   const float* __restrict__ Bm,
                                                   const float* __restrict__ bias,
                                                   float* __restrict__ C, int K) {
    __shared__ __align__(16) float As[64 * 36];  // [m][k], pitch 36
    __shared__ __align__(16) float Bs[64 * 36];  // [n][k] (transposed), pitch 36

    const int tid = threadIdx.x;
    const int tn = tid & 15, tm = tid >> 4;
    const int n0 = blockIdx.x * 64;
    const int m0 = blockIdx.y * 64;
    const int N = gridDim.x * 64;  // 512 (mode 0) or 256 (mode 1) == ldb

    const float* Ap = (MODE == 0) ? A : (const float*)g_hs;

    unsigned long long acc[4][4];
#pragma unroll
    for (int i = 0; i < 4; i++)
#pragma unroll
        for (int j = 0; j < 4; j++) acc[i][j] = 0ULL;

    const int a_m = tid >> 2, a_s = (tid & 3) * 8;  // A staging: 64 rows x 32 cols
    const int b_k = tid >> 3, b_s = (tid & 7) * 8;  // B staging: 32 rows x 64 cols

    for (int k0 = 0; k0 < K; k0 += 32) {
        const float* ap = &Ap[(size_t)(m0 + a_m) * K + k0 + a_s];
        float4 av0 = *(const float4*)(ap);
        float4 av1 = *(const float4*)(ap + 4);
        const float* bp = &Bm[(size_t)(k0 + b_k) * N + n0 + b_s];
        float4 bv0 = *(const float4*)(bp);
        float4 bv1 = *(const float4*)(bp + 4);

        __syncthreads();  // previous tile fully consumed
        *(float4*)&As[a_m * 36 + a_s] = av0;
        *(float4*)&As[a_m * 36 + a_s + 4] = av1;
        Bs[(b_s + 0) * 36 + b_k] = bv0.x;
        Bs[(b_s + 1) * 36 + b_k] = bv0.y;
        Bs[(b_s + 2) * 36 + b_k] = bv0.z;
        Bs[(b_s + 3) * 36 + b_k] = bv0.w;
        Bs[(b_s + 4) * 36 + b_k] = bv1.x;
        Bs[(b_s + 5) * 36 + b_k] = bv1.y;
        Bs[(b_s + 6) * 36 + b_k] = bv1.z;
        Bs[(b_s + 7) * 36 + b_k] = bv1.w;
        __syncthreads();

#pragma unroll
        for (int kk = 0; kk < 32; kk += 4) {
            unsigned long long av[4][2], bv[4][2];
#pragma unroll
            for (int i = 0; i < 4; i++) {
                ulonglong2 t = *(const ulonglong2*)&As[(tm * 4 + i) * 36 + kk];
                av[i][0] = t.x;
                av[i][1] = t.y;
            }
#pragma unroll
            for (int j = 0; j < 4; j++) {
                ulonglong2 t = *(const ulonglong2*)&Bs[(tn + 16 * j) * 36 + kk];
                bv[j][0] = t.x;
                bv[j][1] = t.y;
            }
#pragma unroll
            for (int i = 0; i < 4; i++)
#pragma unroll
                for (int j = 0; j < 4; j++) {
                    fma2(acc[i][j], av[i][0], bv[j][0]);
                    fma2(acc[i][j], av[i][1], bv[j][1]);
                }
        }
    }

#pragma unroll
    for (int j = 0; j < 4; j++) {
        int n = n0 + tn + 16 * j;
        float bz = bias[n];
#pragma unroll
        for (int i = 0; i < 4; i++) {
            int m = m0 + tm * 4 + i;
            float v = f2sum(acc[i][j]) + bz;
            if (MODE == 0) {
                int b = m >> 10, t = m & 1023;  // m = b*1024 + t
                g_xh[((size_t)t * NB + b) * NH + n] = v;
            } else {
                C[(size_t)m * NO + n] = v;
            }
        }
    }
}

// =====================================================================================
// Scan: 16 independent clusters (one per 4-row batch group), 8 CTAs/cluster
// (one per 64-col slice). W_hh slice resident in SMEM for all 1024 steps.
// h exchange: st.async (DSMEM scalar stores with complete_tx) into each peer's
// double-buffered h smem; each CTA's inbox readiness is tracked by a
// transaction-counting mbarrier (2 per CTA, one per buffer). No cluster
// barrier, no fences, no drain-wait on the step-critical path.
// =====================================================================================
__global__ __launch_bounds__(256) __cluster_dims__(8, 1, 1)
void scan_kernel(const float* __restrict__ W_hh) {
    extern __shared__ __align__(16) float smem[];
    float* Ws = smem;                            // [64][516]  c-major, k contiguous
    float* hsm = smem + 64 * 516;                // [2][4][516] double-buffered h
    float* red = smem + 64 * 516 + 2 * 4 * 516;  // [2][16][4][64] double-buffered
    __shared__ __align__(8) unsigned long long mbar[2];

    const int tid = threadIdx.x;
    unsigned s;  // column slice = rank within cluster
    asm("mov.u32 %0, %%cluster_ctarank;" : "=r"(s));
    const int g = blockIdx.x >> 3;            // batch group (4 rows)
    const int cc = tid & 15, ks = tid >> 4;   // compute mapping
    const int rr = tid >> 6, c = tid & 63;    // reduce/io mapping

    const unsigned mbar_base = smem_u32(mbar);
    const unsigned hsm_base = smem_u32(hsm);

    // stage W slice transposed: Ws[c][k] = W_hh[k][s*64+c]
    for (int idx = tid; idx < NH * 64; idx += 256) {
        int k = idx >> 6, cl = idx & 63;
        Ws[cl * 516 + k] = W_hh[(size_t)k * NH + s * 64 + cl];
    }
    // h0 = 0 in both buffers
    for (int idx = tid; idx < 2 * 4 * 516; idx += 256) hsm[idx] = 0.f;
    if (tid == 0) {
        mbar_init(mbar_base, 1);
        mbar_init(mbar_base + 8, 1);
        // pre-arm phase 0 of both: 1 local arrival + 8 KB of incoming tx each
        mbar_arrive_expect_tx(mbar_base, 8192);
        mbar_arrive_expect_tx(mbar_base + 8, 8192);
    }
    __syncthreads();

    // cluster sync: all CTAs' smem zeroed + mbarriers armed before any st.async
    asm volatile("barrier.cluster.arrive.aligned;" ::: "memory");
    asm volatile("barrier.cluster.wait.aligned;" ::: "memory");

    // precompute peer addresses (mapa once, reuse every step)
    unsigned remh[8], remb[8];
#pragma unroll
    for (int p = 0; p < 8; p++) {
        asm("mapa.shared::cluster.u32 %0, %1, %2;"
            : "=r"(remh[p]) : "r"(hsm_base), "r"((unsigned)p));
        asm("mapa.shared::cluster.u32 %0, %1, %2;"
            : "=r"(remb[p]) : "r"(mbar_base), "r"((unsigned)p));
    }

    const int k0 = ks * 32;
    const float* Wp = Ws + cc * 516;
    const unsigned my_elem = (unsigned)(rr * 516 + s * 64 + c) * 4u;

    for (int t = 0; t < NT; t++) {
        // xh prefetch: global read, issued before the FMA block to hide latency
        float xval = g_xh[((size_t)t * NB + g * 4 + rr) * NH + s * 64 + c];

        const float* hcur = hsm + (t & 1) * (4 * 516);
        float* redt = red + (t & 1) * (16 * 4 * 64);

        // partials: thread covers 4 rows x 4 cols (c strided 16) x 32 k
        unsigned long long acc[4][4];
#pragma unroll
        for (int r = 0; r < 4; r++)
#pragma unroll
            for (int cp = 0; cp < 4; cp++) acc[r][cp] = 0ULL;

#pragma unroll
        for (int kk = 0; kk < 32; kk += 4) {
            ulonglong2 hv[4];
#pragma unroll
            for (int r = 0; r < 4; r++)
                hv[r] = *(const ulonglong2*)&hcur[r * 516 + k0 + kk];
#pragma unroll
            for (int cp = 0; cp < 4; cp++) {
                ulonglong2 wv = *(const ulonglong2*)&Wp[cp * (16 * 516) + k0 + kk];
#pragma unroll
                for (int r = 0; r < 4; r++) {
                    fma2(acc[r][cp], wv.x, hv[r].x);
                    fma2(acc[r][cp], wv.y, hv[r].y);
                }
            }
        }
#pragma unroll
        for (int r = 0; r < 4; r++)
#pragma unroll
            for (int cp = 0; cp < 4; cp++)
                redt[(ks * 4 + r) * 64 + cc + 16 * cp] = f2sum(acc[r][cp]);
        __syncthreads();  // the only intra-CTA sync per step (red double-buffered)

        // k-split reduction + tanh
        float v = xval;
#pragma unroll
        for (int q = 0; q < 16; q++) v += redt[(q * 4 + rr) * 64 + c];
        float h = tanhf(v);

        if (t + 1 < NT) {
            // broadcast h into every cluster CTA's NEXT h buffer; each 4-byte
            // st.async signals complete_tx on the destination CTA's mbarrier.
            const unsigned boff = (unsigned)(((t + 1) & 1) * (4 * 516) * 4) + my_elem;
            const unsigned moff = ((t + 1) & 1) * 8u;
#pragma unroll
            for (int p = 0; p < 8; p++)
                st_async_f32(remh[p] + boff, h, remb[p] + moff);
        }

        // persist for the output GEMM (off the critical path)
        g_hs[((size_t)(g * 4 + rr) * NT + t) * NH + s * 64 + c] = h;

        if (t + 1 < NT) {
            // wait until MY inbox for buffer (t+1)&1 is full (8 KB arrived)
            const unsigned mb = mbar_base + ((t + 1) & 1) * 8u;
            mbar_wait_parity(mb, (unsigned)((t >> 1) & 1));
            // re-arm this mbarrier for its next use (step t+2's stores)
            if (tid == 0) mbar_arrive_expect_tx(mb, 8192);
        }
    }

    // all incoming traffic was consumed by the waits above; exit in lockstep
    asm volatile("barrier.cluster.arrive.aligned;" ::: "memory");
    asm volatile("barrier.cluster.wait.aligned;" ::: "memory");
}

// =====================================================================================
extern "C" void kernel_launch(void* const* d_in, const int* in_sizes, int n_in,
                              void* d_out, int out_size) {
    const float* x = (const float*)d_in[0];
    const float* W_xh = (const float*)d_in[1];
    const float* W_hh = (const float*)d_in[2];
    const float* b_h = (const float*)d_in[3];
    const float* W_hy = (const float*)d_in[4];
    const float* b_y = (const float*)d_in[5];
    float* out = (float*)d_out;

    const int scan_smem =
        (64 * 516 + 2 * 4 * 516 + 2 * 16 * 4 * 64) * (int)sizeof(float);
    cudaFuncSetAttribute(scan_kernel, cudaFuncAttributeMaxDynamicSharedMemorySize,
                         scan_smem);

    // xh = x @ W_xh + b_h   (M=65536, N=512, K=256) -> g_xh [t][b][h]
    gemm_kernel<0><<<dim3(8, 1024), 256>>>(x, W_xh, b_h, nullptr, NI);
    // recurrence: 16 clusters x 8 CTAs
    scan_kernel<<<128, 256, scan_smem>>>(W_hh);
    // out = hs @ W_hy + b_y (M=65536, N=256, K=512)
    gemm_kernel<1><<<dim3(4, 1024), 256>>>(nullptr, W_hy, b_y, out, NH);
}